// round 1
// baseline (speedup 1.0000x reference)
#include <cuda_runtime.h>

// Problem constants (fixed by this problem instance; chunk_size input == 512)
#define B_     2
#define S_     2048
#define HQ_    16
#define HKV_   8
#define D_     128
#define GROUP_ 2
#define CHUNK_ 512

#define TQ       64
#define TK       64
#define NTHREADS 256
#define PAD      65   // smem row stride (floats) for transposed Q/K and P

// Scratch for per-position allowed-window bounds (no cudaMalloc allowed)
__device__ int g_lo[B_ * S_];
__device__ int g_hi[B_ * S_];

// ---------------------------------------------------------------------------
// Per-batch scans: prevzero (inclusive max-scan) and nextzero (suffix min-scan)
// give the bidirectional run interval; combined with the chunk-causal interval
// (both contain q) the allowed set is one contiguous window [lo, hi].
// ---------------------------------------------------------------------------
__global__ void mask_scan_kernel(const int* __restrict__ mask) {
    __shared__ int a[S_];
    __shared__ int t[S_];
    const int b = blockIdx.x;
    const int* m = mask + b * S_;

    // prefix-max of (m==0 ? s : -1)  => prevzero[s]
    for (int s = threadIdx.x; s < S_; s += blockDim.x)
        a[s] = (m[s] == 0) ? s : -1;
    __syncthreads();
    for (int off = 1; off < S_; off <<= 1) {
        for (int s = threadIdx.x; s < S_; s += blockDim.x) {
            int v = a[s];
            if (s >= off) v = max(v, a[s - off]);
            t[s] = v;
        }
        __syncthreads();
        for (int s = threadIdx.x; s < S_; s += blockDim.x) a[s] = t[s];
        __syncthreads();
    }
    for (int s = threadIdx.x; s < S_; s += blockDim.x) {
        int cs = (s / CHUNK_) * CHUNK_;
        int lo = cs;
        if (m[s] != 0) lo = min(cs, a[s] + 1);   // run_start = prevzero+1
        g_lo[b * S_ + s] = lo;
    }
    __syncthreads();

    // suffix-min of (m==0 ? s : S_)  => nextzero[s]
    for (int s = threadIdx.x; s < S_; s += blockDim.x)
        a[s] = (m[s] == 0) ? s : S_;
    __syncthreads();
    for (int off = 1; off < S_; off <<= 1) {
        for (int s = threadIdx.x; s < S_; s += blockDim.x) {
            int v = a[s];
            if (s + off < S_) v = min(v, a[s + off]);
            t[s] = v;
        }
        __syncthreads();
        for (int s = threadIdx.x; s < S_; s += blockDim.x) a[s] = t[s];
        __syncthreads();
    }
    for (int s = threadIdx.x; s < S_; s += blockDim.x) {
        int hi = s;
        if (m[s] != 0) hi = max(s, a[s] - 1);    // run_end = nextzero-1
        g_hi[b * S_ + s] = hi;
    }
}

// ---------------------------------------------------------------------------
// Flash-attention over the contiguous per-row window.
// Block: 64 queries x one head. 256 threads.
// QK micro-tile 4x4 (Q,K transposed in smem, conflict-free), PV micro-tile 4x8.
// ---------------------------------------------------------------------------
__global__ __launch_bounds__(NTHREADS, 1)
void attn_kernel(const float* __restrict__ gq, const float* __restrict__ gk,
                 const float* __restrict__ gv, float* __restrict__ gout) {
    const int nqt = S_ / TQ;                  // 32 query tiles per (b,h)
    const int blk = blockIdx.x;
    const int qt  = blk % nqt;
    const int h   = (blk / nqt) % HQ_;
    const int b   = blk / (nqt * HQ_);
    const int kvh = h / GROUP_;
    const int q0  = qt * TQ;

    extern __shared__ float smf[];
    float* Qs = smf;                        // [D_][PAD] transposed: Qs[d][r]
    float* Ks = Qs + D_ * PAD;              // [D_][PAD] transposed: Ks[d][c]
    float* Vs = Ks + D_ * PAD;              // [TK][D_]  row-major
    float* Ps = Vs + TK * D_;               // [TQ][PAD] scores/probs
    float* rowm = Ps + TQ * PAD;            // running max
    float* rowl = rowm + TQ;                // running denom
    float* rowa = rowl + TQ;                // per-tile rescale
    int*   rlo  = (int*)(rowa + TQ);
    int*   rhi  = rlo + TQ;
    __shared__ int s_klo, s_khi;

    const int tid  = threadIdx.x;
    const int lane = tid & 31;
    const int warp = tid >> 5;
    const int tr   = tid >> 4;   // 0..15 (row group)
    const int tc   = tid & 15;   // 0..15 (col group)

    if (tid < TQ) {
        const int qpos = q0 + tid;
        rlo[tid] = g_lo[b * S_ + qpos];
        rhi[tid] = g_hi[b * S_ + qpos];
        rowm[tid] = -1e30f;
        rowl[tid] = 0.f;
    }
    __syncthreads();
    if (tid == 0) {
        int klo = rlo[0], khi = rhi[0];
        #pragma unroll
        for (int i = 1; i < TQ; i++) { klo = min(klo, rlo[i]); khi = max(khi, rhi[i]); }
        s_klo = (klo / TK) * TK;
        s_khi = khi;
    }

    // Load Q tile transposed & pre-scaled. d = lane+32*i keeps STS conflict-free.
    const float scale = 0.088388347648318447f;   // 1/sqrt(128)
    #pragma unroll
    for (int it = 0; it < TQ / 8; ++it) {
        const int r = it * 8 + warp;
        const float* src = gq + (((size_t)b * S_ + (q0 + r)) * HQ_ + h) * D_;
        #pragma unroll
        for (int i = 0; i < 4; ++i) {
            const int d = lane + 32 * i;
            Qs[d * PAD + r] = src[d] * scale;
        }
    }
    __syncthreads();

    int myLo[4], myHi[4];
    #pragma unroll
    for (int i = 0; i < 4; ++i) { myLo[i] = rlo[tr + 16 * i]; myHi[i] = rhi[tr + 16 * i]; }

    float o[4][8];
    #pragma unroll
    for (int i = 0; i < 4; ++i)
        #pragma unroll
        for (int j = 0; j < 8; ++j) o[i][j] = 0.f;

    const int klo = s_klo, khi = s_khi;

    for (int kt = klo; kt <= khi; kt += TK) {
        __syncthreads();   // previous PV reads of Ks/Vs/Ps complete

        // K transposed
        #pragma unroll
        for (int it = 0; it < TK / 8; ++it) {
            const int r = it * 8 + warp;
            const float* src = gk + (((size_t)b * S_ + (kt + r)) * HKV_ + kvh) * D_;
            #pragma unroll
            for (int i = 0; i < 4; ++i) {
                const int d = lane + 32 * i;
                Ks[d * PAD + r] = src[d];
            }
        }
        // V row-major, float4
        #pragma unroll
        for (int it = 0; it < (TK * D_ / 4) / NTHREADS; ++it) {
            const int idx = tid + NTHREADS * it;
            const int r = idx >> 5;
            const int d4 = idx & 31;
            const float4* src = (const float4*)(gv + (((size_t)b * S_ + (kt + r)) * HKV_ + kvh) * D_);
            ((float4*)Vs)[r * 32 + d4] = src[d4];
        }
        __syncthreads();

        // ---- QK: 4x4 per thread ----
        float acc[4][4];
        #pragma unroll
        for (int i = 0; i < 4; ++i)
            #pragma unroll
            for (int j = 0; j < 4; ++j) acc[i][j] = 0.f;

        const float* qb = Qs + tr;
        const float* kb = Ks + tc;
        #pragma unroll 4
        for (int dd = 0; dd < D_; ++dd) {
            float qv[4], kv[4];
            #pragma unroll
            for (int i = 0; i < 4; ++i) qv[i] = qb[dd * PAD + 16 * i];
            #pragma unroll
            for (int j = 0; j < 4; ++j) kv[j] = kb[dd * PAD + 16 * j];
            #pragma unroll
            for (int i = 0; i < 4; ++i)
                #pragma unroll
                for (int j = 0; j < 4; ++j) acc[i][j] = fmaf(qv[i], kv[j], acc[i][j]);
        }
        #pragma unroll
        for (int i = 0; i < 4; ++i) {
            const int r = tr + 16 * i;
            #pragma unroll
            for (int j = 0; j < 4; ++j) {
                const int c = tc + 16 * j;
                const int kpos = kt + c;
                const bool ok = (kpos >= myLo[i]) && (kpos <= myHi[i]);
                Ps[r * PAD + c] = ok ? acc[i][j] : -1e30f;
            }
        }
        __syncthreads();

        // ---- online softmax: 4 threads per row ----
        {
            const int row = tid >> 2;
            const int sub = tid & 3;
            const int rl = rlo[row], rh = rhi[row];
            float sv[16];
            float mloc = -1e30f;
            #pragma unroll
            for (int c0 = 0; c0 < 16; ++c0) {
                sv[c0] = Ps[row * PAD + sub * 16 + c0];
                mloc = fmaxf(mloc, sv[c0]);
            }
            mloc = fmaxf(mloc, __shfl_xor_sync(0xffffffffu, mloc, 1));
            mloc = fmaxf(mloc, __shfl_xor_sync(0xffffffffu, mloc, 2));
            const float mold = rowm[row];
            const float mnew = fmaxf(mold, mloc);
            float sum = 0.f;
            #pragma unroll
            for (int c0 = 0; c0 < 16; ++c0) {
                const int kpos = kt + sub * 16 + c0;
                // force-zero out-of-window cols (handles all-masked-tile degenerate case)
                const float p = (kpos >= rl && kpos <= rh) ? __expf(sv[c0] - mnew) : 0.f;
                Ps[row * PAD + sub * 16 + c0] = p;
                sum += p;
            }
            sum += __shfl_xor_sync(0xffffffffu, sum, 1);
            sum += __shfl_xor_sync(0xffffffffu, sum, 2);
            const float alpha = __expf(mold - mnew);
            if (sub == 0) {
                rowm[row] = mnew;
                rowl[row] = rowl[row] * alpha + sum;
                rowa[row] = alpha;
            }
        }
        __syncthreads();

        // ---- PV: 4x8 per thread ----
        #pragma unroll
        for (int i = 0; i < 4; ++i) {
            const float al = rowa[tr + 16 * i];
            #pragma unroll
            for (int j = 0; j < 8; ++j) o[i][j] *= al;
        }
        const float* pb = Ps + tr * PAD;
        const float* vb = Vs + tc;
        #pragma unroll 2
        for (int kk = 0; kk < TK; ++kk) {
            float pv[4], vv[8];
            #pragma unroll
            for (int i = 0; i < 4; ++i) pv[i] = pb[16 * i * PAD + kk];
            #pragma unroll
            for (int j = 0; j < 8; ++j) vv[j] = vb[kk * D_ + 16 * j];
            #pragma unroll
            for (int i = 0; i < 4; ++i)
                #pragma unroll
                for (int j = 0; j < 8; ++j) o[i][j] = fmaf(pv[i], vv[j], o[i][j]);
        }
    }

    __syncthreads();
    #pragma unroll
    for (int i = 0; i < 4; ++i) {
        const int r = tr + 16 * i;
        const float inv = 1.0f / rowl[r];
        float* dst = gout + (((size_t)b * S_ + (q0 + r)) * HQ_ + h) * D_;
        #pragma unroll
        for (int j = 0; j < 8; ++j)
            dst[tc + 16 * j] = o[i][j] * inv;
    }
}

// ---------------------------------------------------------------------------
extern "C" void kernel_launch(void* const* d_in, const int* in_sizes, int n_in,
                              void* d_out, int out_size) {
    const float* q    = (const float*)d_in[0];
    const float* k    = (const float*)d_in[1];
    const float* v    = (const float*)d_in[2];
    const int*   mask = (const int*)d_in[3];
    float*       out  = (float*)d_out;

    mask_scan_kernel<<<B_, 256>>>(mask);

    const size_t shbytes = (size_t)(2 * D_ * PAD + TK * D_ + TQ * PAD + 3 * TQ + 2 * TQ) * sizeof(float); // 117,248 B
    cudaFuncSetAttribute(attn_kernel, cudaFuncAttributeMaxDynamicSharedMemorySize, (int)shbytes);

    const int grid = B_ * HQ_ * (S_ / TQ);   // 1024 blocks
    attn_kernel<<<grid, NTHREADS, shbytes>>>(q, k, v, out);
}

// round 3
// speedup vs baseline: 3.1729x; 3.1729x over previous
#include <cuda_runtime.h>
#include <cstdint>

// ---------------- problem constants ----------------
#define B_     2
#define S_     2048
#define HQ_    16
#define HKV_   8
#define D_     128
#define GROUP_ 2
#define CHUNK_ 512

#define TQ   64      // query positions per CTA (x2 heads -> M=128 rows)
#define TK   64      // key tile
#define NTH  256     // 8 warps

// smem row strides (floats) — chosen for conflict-free fragment access
#define SQ 132
#define SK 132
#define SV 136
#define SP 68

__device__ int g_lo[B_ * S_];
__device__ int g_hi[B_ * S_];

// ---------------------------------------------------------------------------
static __device__ __forceinline__ uint32_t f2tf(float x) {
    uint32_t y; asm("cvt.rna.tf32.f32 %0, %1;" : "=r"(y) : "f"(x)); return y;
}

static __device__ __forceinline__ void mma8(float* d, const uint32_t* a, const uint32_t* b) {
    asm volatile(
        "mma.sync.aligned.m16n8k8.row.col.f32.tf32.tf32.f32 "
        "{%0,%1,%2,%3}, {%4,%5,%6,%7}, {%8,%9}, {%0,%1,%2,%3};"
        : "+f"(d[0]), "+f"(d[1]), "+f"(d[2]), "+f"(d[3])
        : "r"(a[0]), "r"(a[1]), "r"(a[2]), "r"(a[3]), "r"(b[0]), "r"(b[1]));
}

// ---------------------------------------------------------------------------
// mask scan: allowed set per position collapses to contiguous window [lo,hi]
// ---------------------------------------------------------------------------
__global__ void mask_scan_kernel(const int* __restrict__ mask) {
    __shared__ int a[S_];
    __shared__ int t[S_];
    const int b = blockIdx.x;
    const int* m = mask + b * S_;

    for (int s = threadIdx.x; s < S_; s += blockDim.x) a[s] = (m[s] == 0) ? s : -1;
    __syncthreads();
    for (int off = 1; off < S_; off <<= 1) {
        for (int s = threadIdx.x; s < S_; s += blockDim.x) {
            int v = a[s]; if (s >= off) v = max(v, a[s - off]); t[s] = v;
        }
        __syncthreads();
        for (int s = threadIdx.x; s < S_; s += blockDim.x) a[s] = t[s];
        __syncthreads();
    }
    for (int s = threadIdx.x; s < S_; s += blockDim.x) {
        int cs = (s / CHUNK_) * CHUNK_;
        int lo = cs;
        if (m[s] != 0) lo = min(cs, a[s] + 1);
        g_lo[b * S_ + s] = lo;
    }
    __syncthreads();
    for (int s = threadIdx.x; s < S_; s += blockDim.x) a[s] = (m[s] == 0) ? s : S_;
    __syncthreads();
    for (int off = 1; off < S_; off <<= 1) {
        for (int s = threadIdx.x; s < S_; s += blockDim.x) {
            int v = a[s]; if (s + off < S_) v = min(v, a[s + off]); t[s] = v;
        }
        __syncthreads();
        for (int s = threadIdx.x; s < S_; s += blockDim.x) a[s] = t[s];
        __syncthreads();
    }
    for (int s = threadIdx.x; s < S_; s += blockDim.x) {
        int hi = s;
        if (m[s] != 0) hi = max(s, a[s] - 1);
        g_hi[b * S_ + s] = hi;
    }
}

// ---------------------------------------------------------------------------
// tf32 mma.sync flash attention, single pass, online softmax in registers.
// ---------------------------------------------------------------------------
__global__ __launch_bounds__(NTH, 1)
void attn_mma(const float* __restrict__ gq, const float* __restrict__ gk,
              const float* __restrict__ gv, float* __restrict__ gout) {
    extern __shared__ float sm[];
    float* Qs = sm;                     // [128][SQ] tf32 (row = 64 pos x 2 heads)
    float* Ks = Qs + 128 * SQ;          // [TK][SK]  tf32, row = key pos, col = d
    float* Vs = Ks + TK * SK;           // [TK][SV]  tf32, row = key pos, col = d
    float* Ps = Vs + TK * SV;           // [128][SP] tf32 probs

    __shared__ int rlo_s[64], rhi_s[64];
    __shared__ int s_klo, s_khi;

    const int tid  = threadIdx.x;
    const int lane = tid & 31;
    const int wid  = tid >> 5;
    const int qid  = lane >> 2;       // 0..7
    const int qc   = lane & 3;        // 0..3
    const int wr0  = wid * 16;        // warp's first row

    const int blk = blockIdx.x;
    const int qt  = blk & 31;
    const int kvh = (blk >> 5) & 7;
    const int b   = blk >> 8;
    const int q0  = qt * TQ;

    if (tid == 0) { s_klo = 0x7fffffff; s_khi = 0; }
    __syncthreads();
    if (tid < 64) {
        int lo = g_lo[b * S_ + q0 + tid];
        int hi = g_hi[b * S_ + q0 + tid];
        rlo_s[tid] = lo; rhi_s[tid] = hi;
        atomicMin(&s_klo, lo); atomicMax(&s_khi, hi);
    }

    // ---- load Q tile (128 rows x 128 d), scaled + tf32 ----
    const float scale = 0.088388347648318447f;   // 1/sqrt(128)
    #pragma unroll
    for (int i = 0; i < 16; ++i) {
        int idx = tid + NTH * i;
        int r = idx >> 5, c4 = idx & 31;
        int pos = q0 + (r & 63), head = kvh * GROUP_ + (r >> 6);
        const float4 v = ((const float4*)(gq + (((size_t)b * S_ + pos) * HQ_ + head) * D_))[c4];
        float4 o;
        o.x = __uint_as_float(f2tf(v.x * scale));
        o.y = __uint_as_float(f2tf(v.y * scale));
        o.z = __uint_as_float(f2tf(v.z * scale));
        o.w = __uint_as_float(f2tf(v.w * scale));
        *(float4*)(Qs + r * SQ + 4 * c4) = o;
    }
    __syncthreads();

    const int rA = wr0 + qid;         // first row this thread owns (second is rA+8)
    const int loA = rlo_s[rA & 63],       hiA = rhi_s[rA & 63];
    const int loB = rlo_s[(rA + 8) & 63], hiB = rhi_s[(rA + 8) & 63];

    float O[16][4];
    #pragma unroll
    for (int nf = 0; nf < 16; ++nf)
        #pragma unroll
        for (int j = 0; j < 4; ++j) O[nf][j] = 0.f;
    float m0 = -3.0e38f, m1 = -3.0e38f, l0 = 0.f, l1 = 0.f;

    const int klo = (s_klo / TK) * TK;
    const int khi = s_khi;

    const uint32_t* Qu = (const uint32_t*)Qs;
    const uint32_t* Ku = (const uint32_t*)Ks;
    const uint32_t* Vu = (const uint32_t*)Vs;
    const uint32_t* Pu = (const uint32_t*)Ps;

    for (int kt = klo; kt <= khi; kt += TK) {
        __syncthreads();   // all warps done with prev Ks/Vs

        // ---- load K and V tiles (64 x 128 each), tf32 ----
        #pragma unroll
        for (int i = 0; i < 8; ++i) {
            int idx = tid + NTH * i;
            int r = idx >> 5, c4 = idx & 31;
            const size_t gofs = (((size_t)b * S_ + (kt + r)) * HKV_ + kvh) * D_;
            const float4 kv = ((const float4*)(gk + gofs))[c4];
            float4 ok;
            ok.x = __uint_as_float(f2tf(kv.x)); ok.y = __uint_as_float(f2tf(kv.y));
            ok.z = __uint_as_float(f2tf(kv.z)); ok.w = __uint_as_float(f2tf(kv.w));
            *(float4*)(Ks + r * SK + 4 * c4) = ok;
            const float4 vv = ((const float4*)(gv + gofs))[c4];
            float4 ov;
            ov.x = __uint_as_float(f2tf(vv.x)); ov.y = __uint_as_float(f2tf(vv.y));
            ov.z = __uint_as_float(f2tf(vv.z)); ov.w = __uint_as_float(f2tf(vv.w));
            *(float4*)(Vs + r * SV + 4 * c4) = ov;
        }
        __syncthreads();

        // ---- S = Q K^T  (m16 per warp x n64), 128 HMMA ----
        float Sf[8][4];
        #pragma unroll
        for (int n8 = 0; n8 < 8; ++n8)
            #pragma unroll
            for (int j = 0; j < 4; ++j) Sf[n8][j] = 0.f;

        #pragma unroll
        for (int ks = 0; ks < 16; ++ks) {
            uint32_t a[4];
            const uint32_t* qp = Qu + (wr0 + qid) * SQ + ks * 8 + qc;
            a[0] = qp[0]; a[1] = qp[8 * SQ]; a[2] = qp[4]; a[3] = qp[8 * SQ + 4];
            #pragma unroll
            for (int n8 = 0; n8 < 8; ++n8) {
                uint32_t bb[2];
                const uint32_t* kp = Ku + (n8 * 8 + qid) * SK + ks * 8 + qc;
                bb[0] = kp[0]; bb[1] = kp[4];
                mma8(Sf[n8], a, bb);
            }
        }

        // ---- online softmax on C fragments ----
        float mx0 = m0, mx1 = m1;
        #pragma unroll
        for (int n8 = 0; n8 < 8; ++n8) {
            int kp0 = kt + n8 * 8 + 2 * qc;
            if (kp0     >= loA && kp0     <= hiA) mx0 = fmaxf(mx0, Sf[n8][0]);
            if (kp0 + 1 >= loA && kp0 + 1 <= hiA) mx0 = fmaxf(mx0, Sf[n8][1]);
            if (kp0     >= loB && kp0     <= hiB) mx1 = fmaxf(mx1, Sf[n8][2]);
            if (kp0 + 1 >= loB && kp0 + 1 <= hiB) mx1 = fmaxf(mx1, Sf[n8][3]);
        }
        mx0 = fmaxf(mx0, __shfl_xor_sync(0xffffffffu, mx0, 1));
        mx0 = fmaxf(mx0, __shfl_xor_sync(0xffffffffu, mx0, 2));
        mx1 = fmaxf(mx1, __shfl_xor_sync(0xffffffffu, mx1, 1));
        mx1 = fmaxf(mx1, __shfl_xor_sync(0xffffffffu, mx1, 2));

        const float alpha0 = __expf(m0 - mx0);
        const float alpha1 = __expf(m1 - mx1);
        float sum0 = 0.f, sum1 = 0.f;
        #pragma unroll
        for (int n8 = 0; n8 < 8; ++n8) {
            int kp0 = kt + n8 * 8 + 2 * qc;
            float p00 = (kp0     >= loA && kp0     <= hiA) ? __expf(Sf[n8][0] - mx0) : 0.f;
            float p01 = (kp0 + 1 >= loA && kp0 + 1 <= hiA) ? __expf(Sf[n8][1] - mx0) : 0.f;
            float p10 = (kp0     >= loB && kp0     <= hiB) ? __expf(Sf[n8][2] - mx1) : 0.f;
            float p11 = (kp0 + 1 >= loB && kp0 + 1 <= hiB) ? __expf(Sf[n8][3] - mx1) : 0.f;
            sum0 += p00 + p01;
            sum1 += p10 + p11;
            float2 f0, f1;
            f0.x = __uint_as_float(f2tf(p00)); f0.y = __uint_as_float(f2tf(p01));
            f1.x = __uint_as_float(f2tf(p10)); f1.y = __uint_as_float(f2tf(p11));
            *(float2*)(Ps + rA * SP + n8 * 8 + 2 * qc) = f0;
            *(float2*)(Ps + (rA + 8) * SP + n8 * 8 + 2 * qc) = f1;
        }
        sum0 += __shfl_xor_sync(0xffffffffu, sum0, 1);
        sum0 += __shfl_xor_sync(0xffffffffu, sum0, 2);
        sum1 += __shfl_xor_sync(0xffffffffu, sum1, 1);
        sum1 += __shfl_xor_sync(0xffffffffu, sum1, 2);
        l0 = l0 * alpha0 + sum0;
        l1 = l1 * alpha1 + sum1;
        m0 = mx0; m1 = mx1;

        #pragma unroll
        for (int nf = 0; nf < 16; ++nf) {
            O[nf][0] *= alpha0; O[nf][1] *= alpha0;
            O[nf][2] *= alpha1; O[nf][3] *= alpha1;
        }
        __syncwarp();   // P rows are warp-private: STS -> LDS visibility

        // ---- O += P V  (m16 per warp x n128), 128 HMMA ----
        #pragma unroll
        for (int ks2 = 0; ks2 < 8; ++ks2) {
            uint32_t a[4];
            const uint32_t* pp = Pu + (wr0 + qid) * SP + ks2 * 8 + qc;
            a[0] = pp[0]; a[1] = pp[8 * SP]; a[2] = pp[4]; a[3] = pp[8 * SP + 4];
            #pragma unroll
            for (int nf = 0; nf < 16; ++nf) {
                uint32_t bb[2];
                const uint32_t* vp = Vu + (ks2 * 8 + qc) * SV + nf * 8 + qid;
                bb[0] = vp[0]; bb[1] = vp[4 * SV];
                mma8(O[nf], a, bb);
            }
        }
    }

    // ---- epilogue: O / l -> gmem ----
    const float inv0 = 1.0f / l0;
    const float inv1 = 1.0f / l1;
    const int rB = rA + 8;
    const int posA = q0 + (rA & 63), headA = kvh * GROUP_ + (rA >> 6);
    const int posB = q0 + (rB & 63), headB = kvh * GROUP_ + (rB >> 6);
    float* baseA = gout + (((size_t)b * S_ + posA) * HQ_ + headA) * D_;
    float* baseB = gout + (((size_t)b * S_ + posB) * HQ_ + headB) * D_;
    #pragma unroll
    for (int nf = 0; nf < 16; ++nf) {
        int col = nf * 8 + 2 * qc;
        float2 oa, ob;
        oa.x = O[nf][0] * inv0; oa.y = O[nf][1] * inv0;
        ob.x = O[nf][2] * inv1; ob.y = O[nf][3] * inv1;
        *(float2*)(baseA + col) = oa;
        *(float2*)(baseB + col) = ob;
    }
}

// ---------------------------------------------------------------------------
extern "C" void kernel_launch(void* const* d_in, const int* in_sizes, int n_in,
                              void* d_out, int out_size) {
    const float* q    = (const float*)d_in[0];
    const float* k    = (const float*)d_in[1];
    const float* v    = (const float*)d_in[2];
    const int*   mask = (const int*)d_in[3];
    float*       out  = (float*)d_out;

    mask_scan_kernel<<<B_, 256>>>(mask);

    const int shbytes = (128 * SQ + TK * SK + TK * SV + 128 * SP) * 4;   // 171,008 B
    cudaFuncSetAttribute(attn_mma, cudaFuncAttributeMaxDynamicSharedMemorySize, shbytes);

    const int grid = B_ * HKV_ * (S_ / TQ);   // 512 CTAs
    attn_mma<<<grid, NTH, shbytes>>>(q, k, v, out);
}

// round 4
// speedup vs baseline: 4.9089x; 1.5471x over previous
#include <cuda_runtime.h>
#include <cuda_fp16.h>
#include <cstdint>

// ---------------- problem constants ----------------
#define B_     2
#define S_     2048
#define HQ_    16
#define HKV_   8
#define D_     128
#define GROUP_ 2
#define CHUNK_ 512

#define TQ   64      // query positions per CTA (x2 heads -> M=128 rows)
#define TK   64      // key tile
#define NTH  256     // 8 warps
#define LDK  136     // halves per smem tile row (padded: conflict-free ldmatrix)
#define TILE_HALVES (TK * LDK)            // 8704
#define BUF_BYTES   (2 * TILE_HALVES * 2) // K+V per stage = 34816 B

__device__ int g_lo[B_ * S_];
__device__ int g_hi[B_ * S_];
__device__ __align__(16) __half gK16[B_ * S_ * HKV_ * D_];
__device__ __align__(16) __half gV16[B_ * S_ * HKV_ * D_];

// ---------------- helpers ----------------
static __device__ __forceinline__ uint32_t smem_u32(const void* p) {
    uint32_t a;
    asm("{ .reg .u64 t; cvta.to.shared.u64 t, %1; cvt.u32.u64 %0, t; }" : "=r"(a) : "l"(p));
    return a;
}
static __device__ __forceinline__ void ldm4(uint32_t* r, uint32_t a) {
    asm volatile("ldmatrix.sync.aligned.m8n8.x4.shared.b16 {%0,%1,%2,%3},[%4];"
                 : "=r"(r[0]), "=r"(r[1]), "=r"(r[2]), "=r"(r[3]) : "r"(a));
}
static __device__ __forceinline__ void ldm4t(uint32_t* r, uint32_t a) {
    asm volatile("ldmatrix.sync.aligned.m8n8.x4.trans.shared.b16 {%0,%1,%2,%3},[%4];"
                 : "=r"(r[0]), "=r"(r[1]), "=r"(r[2]), "=r"(r[3]) : "r"(a));
}
static __device__ __forceinline__ void mma16(float* d, const uint32_t* a, const uint32_t* b) {
    asm volatile("mma.sync.aligned.m16n8k16.row.col.f32.f16.f16.f32 "
                 "{%0,%1,%2,%3},{%4,%5,%6,%7},{%8,%9},{%0,%1,%2,%3};"
                 : "+f"(d[0]), "+f"(d[1]), "+f"(d[2]), "+f"(d[3])
                 : "r"(a[0]), "r"(a[1]), "r"(a[2]), "r"(a[3]), "r"(b[0]), "r"(b[1]));
}
static __device__ __forceinline__ uint32_t packh2(float x, float y) {
    __half2 h = __floats2half2_rn(x, y);
    return *(uint32_t*)&h;
}
#define CPA16(dst, src) asm volatile("cp.async.cg.shared.global [%0],[%1],16;" :: "r"(dst), "l"(src))
#define CPCOMMIT()      asm volatile("cp.async.commit_group;" ::: "memory")
#define CPWAIT(n)       asm volatile("cp.async.wait_group %0;" :: "n"(n) : "memory")

// ---------------------------------------------------------------------------
// mask scan: allowed set per position collapses to contiguous window [lo,hi]
// ---------------------------------------------------------------------------
__global__ void mask_scan_kernel(const int* __restrict__ mask) {
    __shared__ int a[S_];
    __shared__ int t[S_];
    const int b = blockIdx.x;
    const int* m = mask + b * S_;

    for (int s = threadIdx.x; s < S_; s += blockDim.x) a[s] = (m[s] == 0) ? s : -1;
    __syncthreads();
    for (int off = 1; off < S_; off <<= 1) {
        for (int s = threadIdx.x; s < S_; s += blockDim.x) {
            int v = a[s]; if (s >= off) v = max(v, a[s - off]); t[s] = v;
        }
        __syncthreads();
        for (int s = threadIdx.x; s < S_; s += blockDim.x) a[s] = t[s];
        __syncthreads();
    }
    for (int s = threadIdx.x; s < S_; s += blockDim.x) {
        int cs = (s / CHUNK_) * CHUNK_;
        int lo = cs;
        if (m[s] != 0) lo = min(cs, a[s] + 1);
        g_lo[b * S_ + s] = lo;
    }
    __syncthreads();
    for (int s = threadIdx.x; s < S_; s += blockDim.x) a[s] = (m[s] == 0) ? s : S_;
    __syncthreads();
    for (int off = 1; off < S_; off <<= 1) {
        for (int s = threadIdx.x; s < S_; s += blockDim.x) {
            int v = a[s]; if (s + off < S_) v = min(v, a[s + off]); t[s] = v;
        }
        __syncthreads();
        for (int s = threadIdx.x; s < S_; s += blockDim.x) a[s] = t[s];
        __syncthreads();
    }
    for (int s = threadIdx.x; s < S_; s += blockDim.x) {
        int hi = s;
        if (m[s] != 0) hi = max(s, a[s] - 1);
        g_hi[b * S_ + s] = hi;
    }
}

// ---------------------------------------------------------------------------
// K/V fp32 -> fp16 preconversion (streamed once)
// ---------------------------------------------------------------------------
__global__ void convert_kv(const float* __restrict__ gk, const float* __restrict__ gv) {
    const int n4 = B_ * S_ * HKV_ * D_ / 4;
    __half2* K2 = (__half2*)gK16;
    __half2* V2 = (__half2*)gV16;
    for (int i = blockIdx.x * blockDim.x + threadIdx.x; i < n4; i += gridDim.x * blockDim.x) {
        float4 a = ((const float4*)gk)[i];
        float4 c = ((const float4*)gv)[i];
        K2[2 * i]     = __floats2half2_rn(a.x, a.y);
        K2[2 * i + 1] = __floats2half2_rn(a.z, a.w);
        V2[2 * i]     = __floats2half2_rn(c.x, c.y);
        V2[2 * i + 1] = __floats2half2_rn(c.z, c.w);
    }
}

// ---------------------------------------------------------------------------
// fp16 mma.sync flash attention: Q fragments in registers, ldmatrix K/V,
// register-resident P (C-frag -> A-frag pack), cp.async double-buffered K/V.
// ---------------------------------------------------------------------------
__global__ __launch_bounds__(NTH, 1)
void attn_h(const float* __restrict__ gq, float* __restrict__ gout) {
    extern __shared__ __align__(16) __half smh[];
    __shared__ int rlo_s[TQ], rhi_s[TQ];
    __shared__ int s_klo, s_khi;

    const int tid  = threadIdx.x;
    const int lane = tid & 31;
    const int wid  = tid >> 5;
    const int qid  = lane >> 2;
    const int qc   = lane & 3;
    const int wr0  = wid * 16;

    const int blk = blockIdx.x;
    const int qt  = blk & 31;
    const int kvh = (blk >> 5) & 7;
    const int b   = blk >> 8;
    const int q0  = qt * TQ;

    if (tid == 0) { s_klo = 0x7fffffff; s_khi = 0; }
    __syncthreads();
    if (tid < TQ) {
        int lo = g_lo[b * S_ + q0 + tid];
        int hi = g_hi[b * S_ + q0 + tid];
        rlo_s[tid] = lo; rhi_s[tid] = hi;
        atomicMin(&s_klo, lo); atomicMax(&s_khi, hi);
    }

    // ---- stage Q (fp32 -> fp16 * scale) into smem [128][LDK] ----
    const float scale = 0.088388347648318447f;   // 1/sqrt(128)
    #pragma unroll
    for (int i = 0; i < 16; ++i) {
        int idx = tid + NTH * i;
        int r = idx >> 5, c4 = idx & 31;
        int pos = q0 + (r & 63), head = kvh * GROUP_ + (r >> 6);
        float4 v = ((const float4*)(gq + (((size_t)b * S_ + pos) * HQ_ + head) * D_))[c4];
        *(__half2*)(smh + r * LDK + 4 * c4)     = __floats2half2_rn(v.x * scale, v.y * scale);
        *(__half2*)(smh + r * LDK + 4 * c4 + 2) = __floats2half2_rn(v.z * scale, v.w * scale);
    }
    __syncthreads();

    // ---- Q A-fragments -> registers (persist whole kernel) ----
    uint32_t Qf[8][4];
    {
        const uint32_t qbase = smem_u32(smh);
        const int Qr = wr0 + (lane & 15);
        const int Qc = (lane >> 4) * 8;
        #pragma unroll
        for (int kb = 0; kb < 8; ++kb)
            ldm4(Qf[kb], qbase + (uint32_t)((Qr * LDK + kb * 16 + Qc) * 2));
    }
    __syncthreads();   // Q staging region now reusable as K/V buffers

    const int rA  = wr0 + qid;
    const int loA = rlo_s[rA & 63],       hiA = rhi_s[rA & 63];
    const int loB = rlo_s[(rA + 8) & 63], hiB = rhi_s[(rA + 8) & 63];
    int wLo = 0x7fffffff, wHi = 0;
    {
        const int p0 = wr0 & 63;
        #pragma unroll
        for (int i = 0; i < 16; ++i) { wLo = min(wLo, rlo_s[p0 + i]); wHi = max(wHi, rhi_s[p0 + i]); }
    }

    float O[16][4];
    #pragma unroll
    for (int nf = 0; nf < 16; ++nf)
        #pragma unroll
        for (int j = 0; j < 4; ++j) O[nf][j] = 0.f;
    float m0 = -3.0e38f, m1 = -3.0e38f, l0 = 0.f, l1 = 0.f;

    const int klo = (s_klo / TK) * TK;
    const int khi = s_khi;
    const int nt  = (khi - klo) / TK + 1;

    const uint32_t sb = smem_u32(smh);
    const int Kn = ((lane >> 4) << 3) + (lane & 7);
    const int Kk = ((lane >> 3) & 1) * 8;
    const int Vk = (lane & 7) + ((lane >> 3) & 1) * 8;
    const int Vn = (lane >> 4) * 8;

    // cp.async tile loader: K+V fp16 tiles into stage buffer
    auto issue = [&](int it, int buf) {
        const int kt = klo + it * TK;
        const uint32_t kdst = sb + (uint32_t)buf * BUF_BYTES;
        const uint32_t vdst = kdst + TILE_HALVES * 2;
        #pragma unroll
        for (int i = 0; i < 4; ++i) {
            int idx = tid + NTH * i;
            int r = idx >> 4, c8 = idx & 15;
            size_t g = (((size_t)b * S_ + kt + r) * HKV_ + kvh) * D_ + 8 * c8;
            uint32_t o = (uint32_t)((r * LDK + 8 * c8) * 2);
            CPA16(kdst + o, gK16 + g);
            CPA16(vdst + o, gV16 + g);
        }
    };

    issue(0, 0); CPCOMMIT();

    for (int it = 0; it < nt; ++it) {
        const int kt  = klo + it * TK;
        const int buf = it & 1;
        if (it + 1 < nt) { issue(it + 1, buf ^ 1); CPCOMMIT(); CPWAIT(1); }
        else             { CPWAIT(0); }
        __syncthreads();

        if (kt <= wHi && kt + TK - 1 >= wLo) {
            const uint32_t kbase = sb + (uint32_t)buf * BUF_BYTES;
            const uint32_t vbase = kbase + TILE_HALVES * 2;

            // ---- S = Q K^T  (m16 x n64 x k128) : 64 HMMA, 32 ldmatrix ----
            float Sf[8][4];
            #pragma unroll
            for (int n8 = 0; n8 < 8; ++n8)
                #pragma unroll
                for (int j = 0; j < 4; ++j) Sf[n8][j] = 0.f;

            #pragma unroll
            for (int j = 0; j < 4; ++j) {
                #pragma unroll
                for (int kb = 0; kb < 8; ++kb) {
                    uint32_t Bv[4];
                    ldm4(Bv, kbase + (uint32_t)(((j * 16 + Kn) * LDK + kb * 16 + Kk) * 2));
                    mma16(Sf[2 * j],     Qf[kb], Bv);
                    mma16(Sf[2 * j + 1], Qf[kb], Bv + 2);
                }
            }

            // ---- online softmax on C fragments ----
            float mx0 = m0, mx1 = m1;
            #pragma unroll
            for (int n8 = 0; n8 < 8; ++n8) {
                int kp0 = kt + n8 * 8 + 2 * qc;
                if (kp0     >= loA && kp0     <= hiA) mx0 = fmaxf(mx0, Sf[n8][0]);
                if (kp0 + 1 >= loA && kp0 + 1 <= hiA) mx0 = fmaxf(mx0, Sf[n8][1]);
                if (kp0     >= loB && kp0     <= hiB) mx1 = fmaxf(mx1, Sf[n8][2]);
                if (kp0 + 1 >= loB && kp0 + 1 <= hiB) mx1 = fmaxf(mx1, Sf[n8][3]);
            }
            mx0 = fmaxf(mx0, __shfl_xor_sync(0xffffffffu, mx0, 1));
            mx0 = fmaxf(mx0, __shfl_xor_sync(0xffffffffu, mx0, 2));
            mx1 = fmaxf(mx1, __shfl_xor_sync(0xffffffffu, mx1, 1));
            mx1 = fmaxf(mx1, __shfl_xor_sync(0xffffffffu, mx1, 2));

            const float alpha0 = __expf(m0 - mx0);
            const float alpha1 = __expf(m1 - mx1);
            float sum0 = 0.f, sum1 = 0.f;
            #pragma unroll
            for (int n8 = 0; n8 < 8; ++n8) {
                int kp0 = kt + n8 * 8 + 2 * qc;
                float p00 = (kp0     >= loA && kp0     <= hiA) ? __expf(Sf[n8][0] - mx0) : 0.f;
                float p01 = (kp0 + 1 >= loA && kp0 + 1 <= hiA) ? __expf(Sf[n8][1] - mx0) : 0.f;
                float p10 = (kp0     >= loB && kp0     <= hiB) ? __expf(Sf[n8][2] - mx1) : 0.f;
                float p11 = (kp0 + 1 >= loB && kp0 + 1 <= hiB) ? __expf(Sf[n8][3] - mx1) : 0.f;
                sum0 += p00 + p01; sum1 += p10 + p11;
                Sf[n8][0] = p00; Sf[n8][1] = p01; Sf[n8][2] = p10; Sf[n8][3] = p11;
            }
            sum0 += __shfl_xor_sync(0xffffffffu, sum0, 1);
            sum0 += __shfl_xor_sync(0xffffffffu, sum0, 2);
            sum1 += __shfl_xor_sync(0xffffffffu, sum1, 1);
            sum1 += __shfl_xor_sync(0xffffffffu, sum1, 2);
            l0 = l0 * alpha0 + sum0;
            l1 = l1 * alpha1 + sum1;
            m0 = mx0; m1 = mx1;

            #pragma unroll
            for (int nf = 0; nf < 16; ++nf) {
                O[nf][0] *= alpha0; O[nf][1] *= alpha0;
                O[nf][2] *= alpha1; O[nf][3] *= alpha1;
            }

            // ---- pack P: C-frag -> A-frag, registers only ----
            uint32_t Pf[4][4];
            #pragma unroll
            for (int k2 = 0; k2 < 4; ++k2) {
                Pf[k2][0] = packh2(Sf[2 * k2][0],     Sf[2 * k2][1]);
                Pf[k2][1] = packh2(Sf[2 * k2][2],     Sf[2 * k2][3]);
                Pf[k2][2] = packh2(Sf[2 * k2 + 1][0], Sf[2 * k2 + 1][1]);
                Pf[k2][3] = packh2(Sf[2 * k2 + 1][2], Sf[2 * k2 + 1][3]);
            }

            // ---- O += P V  (m16 x n128 x k64) : 64 HMMA, 32 ldmatrix.trans ----
            #pragma unroll
            for (int j = 0; j < 8; ++j) {
                #pragma unroll
                for (int k2 = 0; k2 < 4; ++k2) {
                    uint32_t Bv[4];
                    ldm4t(Bv, vbase + (uint32_t)(((k2 * 16 + Vk) * LDK + j * 16 + Vn) * 2));
                    mma16(O[2 * j],     Pf[k2], Bv);
                    mma16(O[2 * j + 1], Pf[k2], Bv + 2);
                }
            }
        }
        __syncthreads();
    }

    // ---- epilogue: O / l -> gmem ----
    const float inv0 = 1.0f / l0;
    const float inv1 = 1.0f / l1;
    const int rB = rA + 8;
    const int posA = q0 + (rA & 63), headA = kvh * GROUP_ + (rA >> 6);
    const int posB = q0 + (rB & 63), headB = kvh * GROUP_ + (rB >> 6);
    float* baseA = gout + (((size_t)b * S_ + posA) * HQ_ + headA) * D_;
    float* baseB = gout + (((size_t)b * S_ + posB) * HQ_ + headB) * D_;
    #pragma unroll
    for (int nf = 0; nf < 16; ++nf) {
        int col = nf * 8 + 2 * qc;
        float2 oa, ob;
        oa.x = O[nf][0] * inv0; oa.y = O[nf][1] * inv0;
        ob.x = O[nf][2] * inv1; ob.y = O[nf][3] * inv1;
        *(float2*)(baseA + col) = oa;
        *(float2*)(baseB + col) = ob;
    }
}

// ---------------------------------------------------------------------------
extern "C" void kernel_launch(void* const* d_in, const int* in_sizes, int n_in,
                              void* d_out, int out_size) {
    const float* q    = (const float*)d_in[0];
    const float* k    = (const float*)d_in[1];
    const float* v    = (const float*)d_in[2];
    const int*   mask = (const int*)d_in[3];
    float*       out  = (float*)d_out;

    mask_scan_kernel<<<B_, 256>>>(mask);
    convert_kv<<<1024, 256>>>(k, v);

    const int shbytes = 2 * BUF_BYTES;   // 69632 B (two K+V stages; Q staging aliases)
    cudaFuncSetAttribute(attn_h, cudaFuncAttributeMaxDynamicSharedMemorySize, shbytes);

    const int grid = B_ * HKV_ * (S_ / TQ);   // 512 CTAs
    attn_h<<<grid, NTH, shbytes>>>(q, out);
}

// round 5
// speedup vs baseline: 6.7271x; 1.3704x over previous
#include <cuda_runtime.h>
#include <cuda_fp16.h>
#include <cstdint>

// ---------------- problem constants ----------------
#define B_     2
#define S_     2048
#define HQ_    16
#define HKV_   8
#define D_     128
#define GROUP_ 2
#define CHUNK_ 512

#define TQ   32      // query positions per CTA (x2 heads -> M=64 rows)
#define TK   64      // key tile
#define NTH  128     // 4 warps
#define LDK  136     // halves per smem tile row (padded: conflict-free ldmatrix)
#define TILE_HALVES (TK * LDK)            // 8704
#define BUF_BYTES   (2 * TILE_HALVES * 2) // K+V per stage = 34816 B

#define NCONV 1024   // convert blocks in the fused setup kernel

__device__ int g_lo[B_ * S_];
__device__ int g_hi[B_ * S_];
__device__ __align__(16) __half gK16[B_ * S_ * HKV_ * D_];
__device__ __align__(16) __half gV16[B_ * S_ * HKV_ * D_];

// ---------------- helpers ----------------
static __device__ __forceinline__ uint32_t smem_u32(const void* p) {
    uint32_t a;
    asm("{ .reg .u64 t; cvta.to.shared.u64 t, %1; cvt.u32.u64 %0, t; }" : "=r"(a) : "l"(p));
    return a;
}
static __device__ __forceinline__ void ldm4(uint32_t* r, uint32_t a) {
    asm volatile("ldmatrix.sync.aligned.m8n8.x4.shared.b16 {%0,%1,%2,%3},[%4];"
                 : "=r"(r[0]), "=r"(r[1]), "=r"(r[2]), "=r"(r[3]) : "r"(a));
}
static __device__ __forceinline__ void ldm4t(uint32_t* r, uint32_t a) {
    asm volatile("ldmatrix.sync.aligned.m8n8.x4.trans.shared.b16 {%0,%1,%2,%3},[%4];"
                 : "=r"(r[0]), "=r"(r[1]), "=r"(r[2]), "=r"(r[3]) : "r"(a));
}
static __device__ __forceinline__ void mma16(float* d, const uint32_t* a, const uint32_t* b) {
    asm volatile("mma.sync.aligned.m16n8k16.row.col.f32.f16.f16.f32 "
                 "{%0,%1,%2,%3},{%4,%5,%6,%7},{%8,%9},{%0,%1,%2,%3};"
                 : "+f"(d[0]), "+f"(d[1]), "+f"(d[2]), "+f"(d[3])
                 : "r"(a[0]), "r"(a[1]), "r"(a[2]), "r"(a[3]), "r"(b[0]), "r"(b[1]));
}
static __device__ __forceinline__ uint32_t packh2(float x, float y) {
    __half2 h = __floats2half2_rn(x, y);
    return *(uint32_t*)&h;
}
#define CPA16(dst, src) asm volatile("cp.async.cg.shared.global [%0],[%1],16;" :: "r"(dst), "l"(src))
#define CPCOMMIT()      asm volatile("cp.async.commit_group;" ::: "memory")
#define CPWAIT(n)       asm volatile("cp.async.wait_group %0;" :: "n"(n) : "memory")

// ---------------------------------------------------------------------------
// Fused setup: blocks [0, NCONV) convert K/V fp32->fp16; blocks NCONV..NCONV+1
// compute the per-position allowed window [lo,hi] via bitmask word-scan.
// ---------------------------------------------------------------------------
__global__ void setup_kernel(const float* __restrict__ gk, const float* __restrict__ gv,
                             const int* __restrict__ mask) {
    if (blockIdx.x < NCONV) {
        const int n4 = B_ * S_ * HKV_ * D_ / 4;
        __half2* K2 = (__half2*)gK16;
        __half2* V2 = (__half2*)gV16;
        for (int i = blockIdx.x * blockDim.x + threadIdx.x; i < n4; i += NCONV * blockDim.x) {
            float4 a = ((const float4*)gk)[i];
            float4 c = ((const float4*)gv)[i];
            K2[2 * i]     = __floats2half2_rn(a.x, a.y);
            K2[2 * i + 1] = __floats2half2_rn(a.z, a.w);
            V2[2 * i]     = __floats2half2_rn(c.x, c.y);
            V2[2 * i + 1] = __floats2half2_rn(c.z, c.w);
        }
        return;
    }

    // ---- mask scan for one batch (64 words x 32 positions) ----
    const int bb = blockIdx.x - NCONV;
    const int* m = mask + bb * S_;
    __shared__ int lw[64];   // inclusive prefix-max of last-zero-in-word
    __shared__ int fw[64];   // inclusive suffix-min of first-zero-in-word
    const int t = threadIdx.x;
    uint32_t z = 0;
    if (t < 64) {
        #pragma unroll
        for (int i = 0; i < 32; ++i)
            z |= (m[32 * t + i] == 0) ? (1u << i) : 0u;
        lw[t] = z ? (32 * t + 31 - __clz(z)) : -1;
        fw[t] = z ? (32 * t + __ffs(z) - 1) : S_;
    }
    __syncthreads();
    #pragma unroll
    for (int off = 1; off < 64; off <<= 1) {
        int vl = 0, vf = 0;
        if (t < 64) {
            vl = lw[t]; if (t >= off) vl = max(vl, lw[t - off]);
            vf = fw[t]; if (t + off < 64) vf = min(vf, fw[t + off]);
        }
        __syncthreads();
        if (t < 64) { lw[t] = vl; fw[t] = vf; }
        __syncthreads();
    }
    if (t < 64) {
        const int base = 32 * t;
        int pz = (t > 0) ? lw[t - 1] : -1;
        #pragma unroll
        for (int i = 0; i < 32; ++i) {
            const int s = base + i;
            const bool isz = (z >> i) & 1;
            if (isz) pz = s;
            const int cs = (s / CHUNK_) * CHUNK_;
            g_lo[bb * S_ + s] = isz ? cs : min(cs, pz + 1);
        }
        int nz = (t < 63) ? fw[t + 1] : S_;
        #pragma unroll
        for (int i = 31; i >= 0; --i) {
            const int s = base + i;
            const bool isz = (z >> i) & 1;
            if (isz) nz = s;
            g_hi[bb * S_ + s] = isz ? s : max(s, nz - 1);
        }
    }
}

// ---------------------------------------------------------------------------
// fp16 mma.sync flash attention: Q fragments in registers, ldmatrix K/V,
// register-resident P, cp.async double-buffered K/V, 2 CTAs/SM.
// ---------------------------------------------------------------------------
__global__ __launch_bounds__(NTH, 2)
void attn_h(const float* __restrict__ gq, float* __restrict__ gout) {
    extern __shared__ __align__(16) __half smh[];
    __shared__ int rlo_s[TQ], rhi_s[TQ];
    __shared__ int s_klo, s_khi;

    const int tid  = threadIdx.x;
    const int lane = tid & 31;
    const int wid  = tid >> 5;
    const int qid  = lane >> 2;
    const int qc   = lane & 3;
    const int wr0  = wid * 16;

    const int blk = blockIdx.x;
    const int qt  = blk & 63;
    const int kvh = (blk >> 6) & 7;
    const int b   = blk >> 9;
    const int q0  = qt * TQ;

    if (tid == 0) { s_klo = 0x7fffffff; s_khi = 0; }
    __syncthreads();
    if (tid < TQ) {
        int lo = g_lo[b * S_ + q0 + tid];
        int hi = g_hi[b * S_ + q0 + tid];
        rlo_s[tid] = lo; rhi_s[tid] = hi;
        atomicMin(&s_klo, lo); atomicMax(&s_khi, hi);
    }

    // ---- stage Q (fp32 -> fp16 * scale) into smem [64][LDK] ----
    const float scale = 0.088388347648318447f;   // 1/sqrt(128)
    #pragma unroll
    for (int i = 0; i < 16; ++i) {
        int idx = tid + NTH * i;
        int r = idx >> 5, c4 = idx & 31;
        int pos = q0 + (r & 31), head = kvh * GROUP_ + (r >> 5);
        float4 v = ((const float4*)(gq + (((size_t)b * S_ + pos) * HQ_ + head) * D_))[c4];
        *(__half2*)(smh + r * LDK + 4 * c4)     = __floats2half2_rn(v.x * scale, v.y * scale);
        *(__half2*)(smh + r * LDK + 4 * c4 + 2) = __floats2half2_rn(v.z * scale, v.w * scale);
    }
    __syncthreads();

    // ---- Q A-fragments -> registers (persist whole kernel) ----
    uint32_t Qf[8][4];
    {
        const uint32_t qbase = smem_u32(smh);
        const int Qr = wr0 + (lane & 15);
        const int Qc = (lane >> 4) * 8;
        #pragma unroll
        for (int kb = 0; kb < 8; ++kb)
            ldm4(Qf[kb], qbase + (uint32_t)((Qr * LDK + kb * 16 + Qc) * 2));
    }
    __syncthreads();   // Q staging region now reusable as K/V buffers

    const int rA  = wr0 + qid;
    const int loA = rlo_s[rA & 31],       hiA = rhi_s[rA & 31];
    const int loB = rlo_s[(rA + 8) & 31], hiB = rhi_s[(rA + 8) & 31];
    int wLo = 0x7fffffff, wHi = 0;        // union of warp rows
    int wLoMax = 0, wHiMin = 0x7fffffff;  // intersection (for fast path)
    {
        const int p0 = wr0 & 31;
        #pragma unroll
        for (int i = 0; i < 16; ++i) {
            wLo = min(wLo, rlo_s[p0 + i]); wHi = max(wHi, rhi_s[p0 + i]);
            wLoMax = max(wLoMax, rlo_s[p0 + i]); wHiMin = min(wHiMin, rhi_s[p0 + i]);
        }
    }

    float O[16][4];
    #pragma unroll
    for (int nf = 0; nf < 16; ++nf)
        #pragma unroll
        for (int j = 0; j < 4; ++j) O[nf][j] = 0.f;
    float m0 = -3.0e38f, m1 = -3.0e38f, l0 = 0.f, l1 = 0.f;

    const int klo = (s_klo / TK) * TK;
    const int khi = s_khi;
    const int nt  = (khi - klo) / TK + 1;

    const uint32_t sb = smem_u32(smh);
    const int Kn = ((lane >> 4) << 3) + (lane & 7);
    const int Kk = ((lane >> 3) & 1) * 8;
    const int Vk = (lane & 7) + ((lane >> 3) & 1) * 8;
    const int Vn = (lane >> 4) * 8;

    auto issue = [&](int it, int buf) {
        const int kt = klo + it * TK;
        const uint32_t kdst = sb + (uint32_t)buf * BUF_BYTES;
        const uint32_t vdst = kdst + TILE_HALVES * 2;
        #pragma unroll
        for (int i = 0; i < 8; ++i) {
            int idx = tid + NTH * i;
            int r = idx >> 4, c8 = idx & 15;
            size_t g = (((size_t)b * S_ + kt + r) * HKV_ + kvh) * D_ + 8 * c8;
            uint32_t o = (uint32_t)((r * LDK + 8 * c8) * 2);
            CPA16(kdst + o, gK16 + g);
            CPA16(vdst + o, gV16 + g);
        }
    };

    issue(0, 0); CPCOMMIT();

    for (int it = 0; it < nt; ++it) {
        const int kt  = klo + it * TK;
        const int buf = it & 1;
        if (it + 1 < nt) { issue(it + 1, buf ^ 1); CPCOMMIT(); CPWAIT(1); }
        else             { CPWAIT(0); }
        __syncthreads();

        if (kt <= wHi && kt + TK - 1 >= wLo) {
            const uint32_t kbase = sb + (uint32_t)buf * BUF_BYTES;
            const uint32_t vbase = kbase + TILE_HALVES * 2;
            const bool full = (kt >= wLoMax) && (kt + TK - 1 <= wHiMin); // warp-uniform

            // ---- S = Q K^T ----
            float Sf[8][4];
            #pragma unroll
            for (int n8 = 0; n8 < 8; ++n8)
                #pragma unroll
                for (int j = 0; j < 4; ++j) Sf[n8][j] = 0.f;

            #pragma unroll
            for (int j = 0; j < 4; ++j) {
                #pragma unroll
                for (int kb = 0; kb < 8; ++kb) {
                    uint32_t Bv[4];
                    ldm4(Bv, kbase + (uint32_t)(((j * 16 + Kn) * LDK + kb * 16 + Kk) * 2));
                    mma16(Sf[2 * j],     Qf[kb], Bv);
                    mma16(Sf[2 * j + 1], Qf[kb], Bv + 2);
                }
            }

            // ---- online softmax on C fragments ----
            float mx0 = m0, mx1 = m1;
            float sum0 = 0.f, sum1 = 0.f;
            if (full) {
                #pragma unroll
                for (int n8 = 0; n8 < 8; ++n8) {
                    mx0 = fmaxf(mx0, fmaxf(Sf[n8][0], Sf[n8][1]));
                    mx1 = fmaxf(mx1, fmaxf(Sf[n8][2], Sf[n8][3]));
                }
                mx0 = fmaxf(mx0, __shfl_xor_sync(0xffffffffu, mx0, 1));
                mx0 = fmaxf(mx0, __shfl_xor_sync(0xffffffffu, mx0, 2));
                mx1 = fmaxf(mx1, __shfl_xor_sync(0xffffffffu, mx1, 1));
                mx1 = fmaxf(mx1, __shfl_xor_sync(0xffffffffu, mx1, 2));
                #pragma unroll
                for (int n8 = 0; n8 < 8; ++n8) {
                    float p00 = __expf(Sf[n8][0] - mx0);
                    float p01 = __expf(Sf[n8][1] - mx0);
                    float p10 = __expf(Sf[n8][2] - mx1);
                    float p11 = __expf(Sf[n8][3] - mx1);
                    sum0 += p00 + p01; sum1 += p10 + p11;
                    Sf[n8][0] = p00; Sf[n8][1] = p01; Sf[n8][2] = p10; Sf[n8][3] = p11;
                }
            } else {
                #pragma unroll
                for (int n8 = 0; n8 < 8; ++n8) {
                    int kp0 = kt + n8 * 8 + 2 * qc;
                    if (kp0     >= loA && kp0     <= hiA) mx0 = fmaxf(mx0, Sf[n8][0]);
                    if (kp0 + 1 >= loA && kp0 + 1 <= hiA) mx0 = fmaxf(mx0, Sf[n8][1]);
                    if (kp0     >= loB && kp0     <= hiB) mx1 = fmaxf(mx1, Sf[n8][2]);
                    if (kp0 + 1 >= loB && kp0 + 1 <= hiB) mx1 = fmaxf(mx1, Sf[n8][3]);
                }
                mx0 = fmaxf(mx0, __shfl_xor_sync(0xffffffffu, mx0, 1));
                mx0 = fmaxf(mx0, __shfl_xor_sync(0xffffffffu, mx0, 2));
                mx1 = fmaxf(mx1, __shfl_xor_sync(0xffffffffu, mx1, 1));
                mx1 = fmaxf(mx1, __shfl_xor_sync(0xffffffffu, mx1, 2));
                #pragma unroll
                for (int n8 = 0; n8 < 8; ++n8) {
                    int kp0 = kt + n8 * 8 + 2 * qc;
                    float p00 = (kp0     >= loA && kp0     <= hiA) ? __expf(Sf[n8][0] - mx0) : 0.f;
                    float p01 = (kp0 + 1 >= loA && kp0 + 1 <= hiA) ? __expf(Sf[n8][1] - mx0) : 0.f;
                    float p10 = (kp0     >= loB && kp0     <= hiB) ? __expf(Sf[n8][2] - mx1) : 0.f;
                    float p11 = (kp0 + 1 >= loB && kp0 + 1 <= hiB) ? __expf(Sf[n8][3] - mx1) : 0.f;
                    sum0 += p00 + p01; sum1 += p10 + p11;
                    Sf[n8][0] = p00; Sf[n8][1] = p01; Sf[n8][2] = p10; Sf[n8][3] = p11;
                }
            }
            sum0 += __shfl_xor_sync(0xffffffffu, sum0, 1);
            sum0 += __shfl_xor_sync(0xffffffffu, sum0, 2);
            sum1 += __shfl_xor_sync(0xffffffffu, sum1, 1);
            sum1 += __shfl_xor_sync(0xffffffffu, sum1, 2);
            const float alpha0 = __expf(m0 - mx0);
            const float alpha1 = __expf(m1 - mx1);
            l0 = l0 * alpha0 + sum0;
            l1 = l1 * alpha1 + sum1;
            m0 = mx0; m1 = mx1;

            #pragma unroll
            for (int nf = 0; nf < 16; ++nf) {
                O[nf][0] *= alpha0; O[nf][1] *= alpha0;
                O[nf][2] *= alpha1; O[nf][3] *= alpha1;
            }

            // ---- pack P: C-frag -> A-frag, registers only ----
            uint32_t Pf[4][4];
            #pragma unroll
            for (int k2 = 0; k2 < 4; ++k2) {
                Pf[k2][0] = packh2(Sf[2 * k2][0],     Sf[2 * k2][1]);
                Pf[k2][1] = packh2(Sf[2 * k2][2],     Sf[2 * k2][3]);
                Pf[k2][2] = packh2(Sf[2 * k2 + 1][0], Sf[2 * k2 + 1][1]);
                Pf[k2][3] = packh2(Sf[2 * k2 + 1][2], Sf[2 * k2 + 1][3]);
            }

            // ---- O += P V ----
            #pragma unroll
            for (int j = 0; j < 8; ++j) {
                #pragma unroll
                for (int k2 = 0; k2 < 4; ++k2) {
                    uint32_t Bv[4];
                    ldm4t(Bv, vbase + (uint32_t)(((k2 * 16 + Vk) * LDK + j * 16 + Vn) * 2));
                    mma16(O[2 * j],     Pf[k2], Bv);
                    mma16(O[2 * j + 1], Pf[k2], Bv + 2);
                }
            }
        }
        __syncthreads();
    }

    // ---- epilogue: O / l -> gmem ----
    const float inv0 = 1.0f / l0;
    const float inv1 = 1.0f / l1;
    const int rB = rA + 8;
    const int posA = q0 + (rA & 31), headA = kvh * GROUP_ + (rA >> 5);
    const int posB = q0 + (rB & 31), headB = kvh * GROUP_ + (rB >> 5);
    float* baseA = gout + (((size_t)b * S_ + posA) * HQ_ + headA) * D_;
    float* baseB = gout + (((size_t)b * S_ + posB) * HQ_ + headB) * D_;
    #pragma unroll
    for (int nf = 0; nf < 16; ++nf) {
        int col = nf * 8 + 2 * qc;
        float2 oa, ob;
        oa.x = O[nf][0] * inv0; oa.y = O[nf][1] * inv0;
        ob.x = O[nf][2] * inv1; ob.y = O[nf][3] * inv1;
        *(float2*)(baseA + col) = oa;
        *(float2*)(baseB + col) = ob;
    }
}

// ---------------------------------------------------------------------------
extern "C" void kernel_launch(void* const* d_in, const int* in_sizes, int n_in,
                              void* d_out, int out_size) {
    const float* q    = (const float*)d_in[0];
    const float* k    = (const float*)d_in[1];
    const float* v    = (const float*)d_in[2];
    const int*   mask = (const int*)d_in[3];
    float*       out  = (float*)d_out;

    setup_kernel<<<NCONV + B_, 256>>>(k, v, mask);

    const int shbytes = 2 * BUF_BYTES;   // 69632 B per CTA (2 stages; Q staging aliases)
    cudaFuncSetAttribute(attn_h, cudaFuncAttributeMaxDynamicSharedMemorySize, shbytes);

    const int grid = B_ * HKV_ * (S_ / TQ);   // 1024 CTAs
    attn_h<<<grid, NTH, shbytes>>>(q, out);
}